// round 16
// baseline (speedup 1.0000x reference)
#include <cuda_runtime.h>
#include <math.h>

namespace {
constexpr int B_ = 8, L_ = 256, H_ = 256, NH = 4, D_ = 64, NBLK = 2;
constexpr int ROWS = B_ * L_;          // 2048
constexpr int PLANE = ROWS * H_;       // 524288
constexpr int TT = 513;                // TSPAN+1 time rows
constexpr int TP = 576;                // padded
}

// ---- scratch ----
__device__ float g_x[PLANE];
__device__ float g_q[PLANE];
__device__ float g_Q[PLANE];
__device__ float g_K[PLANE];
__device__ float g_V[PLANE];
__device__ float g_att[PLANE];
__device__ float g_xa[PLANE];
__device__ float g_h[PLANE];
__device__ float g_qtk[NH * ROWS * TP];      // QtK table [h][bq][t]
__device__ float g_w[NH * ROWS * TP];        // histogram weights (.bss zero; pad never written)
__device__ unsigned char g_mask[ROWS];

// GEMM job with optional fused LayerNorm on A.
// If doLN: A_eff = LN(A (+A2)) * gamma + beta; blocks with blockIdx.x==0 also
// write A_eff (fp32) to lnout.
struct TJob {
    const float* A; const float* A2;
    const float* gamma; const float* beta; float* lnout; int doLN;
    const float* W; const float* bias; const float* aux; float* C; int mode;
};
struct TJobs { TJob j[3]; };

// ---- mask dtype sniffer + converter ----
__global__ void k_mask_convert(const void* __restrict__ mraw) {
    __shared__ int s_f32, s_u8;
    const unsigned int* w = (const unsigned int*)mraw;
    int t = threadIdx.x;
    if (t == 0) { s_f32 = 0; s_u8 = 0; }
    __syncthreads();
    for (int i = t; i < 512; i += 256) {
        unsigned int v = w[i];
        if (v == 0x3F800000u) atomicOr(&s_f32, 1);
        if (v & 0xFFFFFF00u)  atomicOr(&s_u8, 1);
    }
    __syncthreads();
    int mode = s_f32 ? 2 : (s_u8 ? 0 : 1);
    const unsigned char* u8 = (const unsigned char*)mraw;
    const int* i32 = (const int*)mraw;
    const float* f32 = (const float*)mraw;
    for (int i = t; i < ROWS; i += 256) {
        unsigned char m;
        if (mode == 0)      m = u8[i] ? 1 : 0;
        else if (mode == 1) m = i32[i] ? 1 : 0;
        else                m = (f32[i] != 0.f) ? 1 : 0;
        g_mask[i] = m;
    }
}

__global__ void k_maskmul(const float* __restrict__ e) {
    int i = blockIdx.x * blockDim.x + threadIdx.x;
    g_x[i] = g_mask[i >> 8] ? 0.f : e[i];
}

// out = LN(in1 (+ in2)) * g + b  — warp per row (used only for the final LN).
__global__ __launch_bounds__(256) void k_ln(const float* __restrict__ in1,
                                            const float* __restrict__ in2,
                                            const float* __restrict__ gg,
                                            const float* __restrict__ bb,
                                            float* __restrict__ out) {
    int row = blockIdx.x * 8 + (threadIdx.x >> 5);
    int lane = threadIdx.x & 31;
    const float* p1 = in1 + row * H_;
    float v[8];
    float s = 0.f;
    #pragma unroll
    for (int j = 0; j < 8; j++) {
        v[j] = p1[lane + 32 * j];
        if (in2) v[j] += in2[row * H_ + lane + 32 * j];
        s += v[j];
    }
    #pragma unroll
    for (int o = 16; o; o >>= 1) s += __shfl_xor_sync(~0u, s, o);
    float m = s * (1.f / H_);
    float sq = 0.f;
    #pragma unroll
    for (int j = 0; j < 8; j++) { float d = v[j] - m; sq += d * d; }
    #pragma unroll
    for (int o = 16; o; o >>= 1) sq += __shfl_xor_sync(~0u, sq, o);
    float inv = rsqrtf(sq * (1.f / H_) + 1e-8f);
    #pragma unroll
    for (int j = 0; j < 8; j++) {
        int c = lane + 32 * j;
        out[row * H_ + c] = (v[j] - m) * inv * gg[c] + bb[c];
    }
}

// ---- tf32 mma helpers ----
__device__ __forceinline__ unsigned f2tf(float f) {
    unsigned u;
    asm("cvt.rna.tf32.f32 %0, %1;" : "=r"(u) : "f"(f));
    return u;
}
__device__ __forceinline__ void mma8(float* d, unsigned a0, unsigned a1,
                                     unsigned a2, unsigned a3,
                                     unsigned b0, unsigned b1) {
    asm volatile(
        "mma.sync.aligned.m16n8k8.row.col.f32.tf32.tf32.f32 "
        "{%0,%1,%2,%3}, {%4,%5,%6,%7}, {%8,%9}, {%0,%1,%2,%3};"
        : "+f"(d[0]), "+f"(d[1]), "+f"(d[2]), "+f"(d[3])
        : "r"(a0), "r"(a1), "r"(a2), "r"(a3), "r"(b0), "r"(b1));
}

// PLAIN tf32 GEMM with OPTIONAL FUSED LayerNorm on A.
// 32x64 block tile, 4 warps (warp 16x32). A staged ONCE (full K) in smem;
// W double-buffered per K-tile (one sync per tile).
__global__ __launch_bounds__(128) void k_gemm_tc(TJobs jobs) {
    const TJob J = jobs.j[blockIdx.z];
    __shared__ unsigned Af[32][260];          // full-A row, tf32 bits (33 KB)
    __shared__ unsigned Ws[2][64][36];        // W double buffer (18 KB)
    int tid = threadIdx.x;
    int w = tid >> 5, lane = tid & 31;
    int wm = w & 1, wn = w >> 1;
    int o0 = blockIdx.x * 64, i0 = blockIdx.y * 32;
    int g = lane >> 2, t4 = lane & 3;

    // ---- stage A (full 32x256), optional LN ----
    {
        int r = tid >> 2, q4 = tid & 3;       // 4 threads per row, 64 cols each
        const float* ap = J.A + (i0 + r) * H_ + q4 * 64;
        float* Aff = (float*)&Af[r][q4 * 64];
        float s = 0.f;
        #pragma unroll
        for (int j = 0; j < 16; j++) {
            float4 v = *(const float4*)(ap + 4 * j);
            if (J.A2) {
                const float* a2 = J.A2 + (i0 + r) * H_ + q4 * 64 + 4 * j;
                v.x += a2[0]; v.y += a2[1]; v.z += a2[2]; v.w += a2[3];
            }
            *(float4*)(Aff + 4 * j) = v;
            s += v.x + v.y + v.z + v.w;
        }
        if (J.doLN) {
            // reduce sum within 4-lane row group
            s += __shfl_xor_sync(~0u, s, 1);
            s += __shfl_xor_sync(~0u, s, 2);
            float m = s * (1.f / H_);
            float sq = 0.f;
            #pragma unroll
            for (int j = 0; j < 64; j++) { float d = Aff[j] - m; sq += d * d; }
            sq += __shfl_xor_sync(~0u, sq, 1);
            sq += __shfl_xor_sync(~0u, sq, 2);
            float inv = rsqrtf(sq * (1.f / H_) + 1e-8f);
            bool wr = (blockIdx.x == 0);
            float* lo = J.lnout + (i0 + r) * H_ + q4 * 64;
            #pragma unroll
            for (int j = 0; j < 64; j++) {
                int c = q4 * 64 + j;
                float lv = (Aff[j] - m) * inv * J.gamma[c] + J.beta[c];
                if (wr) lo[j] = lv;
                Af[r][c] = f2tf(lv);
            }
        } else {
            #pragma unroll
            for (int j = 0; j < 64; j++)
                Af[r][q4 * 64 + j] = f2tf(Aff[j]);
        }
    }

    // ---- W staging (double buffer) + mma ----
    int wsr = tid >> 1, wsc = (tid & 1) * 16;
    const float* Wp = J.W + (o0 + wsr) * H_ + wsc;
    float4 wv[4];
    #pragma unroll
    for (int j = 0; j < 4; j++) wv[j] = *(const float4*)(Wp + 4 * j);

    float acc[4][4] = {};
    #pragma unroll
    for (int tile = 0; tile < 8; tile++) {
        int buf = tile & 1;
        #pragma unroll
        for (int j = 0; j < 4; j++) {
            int c = wsc + 4 * j;
            Ws[buf][wsr][c + 0] = f2tf(wv[j].x); Ws[buf][wsr][c + 1] = f2tf(wv[j].y);
            Ws[buf][wsr][c + 2] = f2tf(wv[j].z); Ws[buf][wsr][c + 3] = f2tf(wv[j].w);
        }
        __syncthreads();
        if (tile < 7) {
            #pragma unroll
            for (int j = 0; j < 4; j++)
                wv[j] = *(const float4*)(Wp + (tile + 1) * 32 + 4 * j);
        }
        int kb = tile * 32;
        #pragma unroll
        for (int kk = 0; kk < 32; kk += 8) {
            int ar0 = wm * 16 + g, ar1 = ar0 + 8;
            unsigned a0 = Af[ar0][kb + kk + t4],     a1 = Af[ar1][kb + kk + t4];
            unsigned a2 = Af[ar0][kb + kk + t4 + 4], a3 = Af[ar1][kb + kk + t4 + 4];
            #pragma unroll
            for (int nf = 0; nf < 4; nf++) {
                int nb = wn * 32 + nf * 8 + g;
                mma8(acc[nf], a0, a1, a2, a3,
                     Ws[buf][nb][kk + t4], Ws[buf][nb][kk + t4 + 4]);
            }
        }
    }

    int mode = J.mode;
    int row0 = i0 + wm * 16 + g, row1 = row0 + 8;
    #pragma unroll
    for (int nf = 0; nf < 4; nf++) {
        int col = o0 + wn * 32 + nf * 8 + 2 * t4;
        float b0 = J.bias[col], b1 = J.bias[col + 1];
        float v00 = acc[nf][0] + b0, v01 = acc[nf][1] + b1;
        float v10 = acc[nf][2] + b0, v11 = acc[nf][3] + b1;
        if (mode == 1 || mode == 2) {
            const float* pos = J.aux;
            v00 += pos[((row0 & 255) << 8) | col];
            v01 += pos[((row0 & 255) << 8) | (col + 1)];
            v10 += pos[((row1 & 255) << 8) | col];
            v11 += pos[((row1 & 255) << 8) | (col + 1)];
        } else if (mode == 3) {
            v00 = fmaxf(v00, 0.f); v01 = fmaxf(v01, 0.f);
            v10 = fmaxf(v10, 0.f); v11 = fmaxf(v11, 0.f);
        } else if (mode == 4) {
            v00 += J.aux[row0 * H_ + col]; v01 += J.aux[row0 * H_ + col + 1];
            v10 += J.aux[row1 * H_ + col]; v11 += J.aux[row1 * H_ + col + 1];
            if (g_mask[row0]) { v00 = 0.f; v01 = 0.f; }
            if (g_mask[row1]) { v10 = 0.f; v11 = 0.f; }
        }
        *(float2*)(J.C + row0 * H_ + col) = make_float2(v00, v01);
        *(float2*)(J.C + row1 * H_ + col) = make_float2(v10, v11);
    }
}

// QtK table, PLAIN tf32; no g_w zeroing (pad stays .bss zero forever).
__global__ __launch_bounds__(256) void k_qtk(const float* __restrict__ tK) {
    __shared__ unsigned As[64][36], Ws[64][36];
    int h = blockIdx.z, hd = h << 6;
    int t0 = blockIdx.x * 64, i0 = blockIdx.y * 64;
    int tid = threadIdx.x;
    int w = tid >> 5, lane = tid & 31;
    int wm = w & 3, wn = w >> 2;
    int g = lane >> 2, t4 = lane & 3;
    int sr = tid >> 2, sc = (tid & 3) * 8;
    float acc[4][4] = {};
    #pragma unroll
    for (int tile = 0; tile < 2; tile++) {
        int kb = tile * 32;
        float4 av0 = *(const float4*)(g_Q + (i0 + sr) * H_ + hd + kb + sc);
        float4 av1 = *(const float4*)(g_Q + (i0 + sr) * H_ + hd + kb + sc + 4);
        int trow = t0 + sr;
        float4 wv0 = make_float4(0.f, 0.f, 0.f, 0.f), wv1 = wv0;
        if (trow < TT) {
            wv0 = *(const float4*)(tK + trow * H_ + hd + kb + sc);
            wv1 = *(const float4*)(tK + trow * H_ + hd + kb + sc + 4);
        }
        float abuf[8] = {av0.x, av0.y, av0.z, av0.w, av1.x, av1.y, av1.z, av1.w};
        float wbuf[8] = {wv0.x, wv0.y, wv0.z, wv0.w, wv1.x, wv1.y, wv1.z, wv1.w};
        #pragma unroll
        for (int j = 0; j < 8; j++) {
            As[sr][sc + j] = f2tf(abuf[j]);
            Ws[sr][sc + j] = f2tf(wbuf[j]);
        }
        __syncthreads();
        #pragma unroll
        for (int kk = 0; kk < 32; kk += 8) {
            int ar0 = wm * 16 + g, ar1 = ar0 + 8;
            unsigned a0 = As[ar0][kk + t4],     a1 = As[ar1][kk + t4];
            unsigned a2 = As[ar0][kk + t4 + 4], a3 = As[ar1][kk + t4 + 4];
            #pragma unroll
            for (int nf = 0; nf < 4; nf++) {
                int nb = wn * 32 + nf * 8 + g;
                mma8(acc[nf], a0, a1, a2, a3, Ws[nb][kk + t4], Ws[nb][kk + t4 + 4]);
            }
        }
        __syncthreads();
    }
    int row0 = i0 + wm * 16 + g, row1 = row0 + 8;
    #pragma unroll
    for (int nf = 0; nf < 4; nf++) {
        int col = t0 + wn * 32 + nf * 8 + 2 * t4;
        int ia = (h * ROWS + row0) * TP + col;
        int ib = (h * ROWS + row1) * TP + col;
        *(float2*)(g_qtk + ia) = make_float2(acc[nf][0], acc[nf][1]);
        *(float2*)(g_qtk + ib) = make_float2(acc[nf][2], acc[nf][3]);
    }
}

// ===== Fused attention core: S=QK^T -> softmax(+qtk) -> histogram ->
//       out = P@V + w@tV. Block per (64q-tile, b, h). =====
constexpr int SMEM_ATTN2 = (256 * 68 + 64 * 260) * 4;
__global__ __launch_bounds__(512) void k_attn2(const int* __restrict__ tm,
                                               const float* __restrict__ tV) {
    extern __shared__ unsigned sm2[];
    unsigned* R1 = sm2;                 // 256*68 words
    unsigned* R2 = sm2 + 256 * 68;      // 64*260 words
    float*    Sf = (float*)R1;
    unsigned* Ks = R1;
    unsigned* Qh = R2;
    float*  hist = (float*)R2;
    unsigned* Vs = R2;

    int qt0 = blockIdx.x * 64;
    int b = blockIdx.y, h = blockIdx.z, hd = h << 6;
    int tid = threadIdx.x, w = tid >> 5, lane = tid & 31;
    int g = lane >> 2, t4 = lane & 3;
    int wm = w & 3, wn = w >> 2;

    {
        int sr = tid >> 3, sc = (tid & 7) * 8;
        const float* qp = g_Q + (((b << 8) | (qt0 + sr)) << 8) + hd + sc;
        float4 v0 = *(const float4*)qp, v1 = *(const float4*)(qp + 4);
        float buf[8] = {v0.x, v0.y, v0.z, v0.w, v1.x, v1.y, v1.z, v1.w};
        #pragma unroll
        for (int j = 0; j < 8; j++)
            Qh[sr * 68 + sc + j] = f2tf(buf[j]);
    }
    {
        int r = tid >> 1, cb = (tid & 1) * 32;
        const float* kp = g_K + (((b << 8) | r) << 8) + hd + cb;
        #pragma unroll
        for (int j = 0; j < 8; j++) {
            float4 kv = *(const float4*)(kp + 4 * j);
            int o = r * 68 + cb + 4 * j;
            Ks[o + 0] = f2tf(kv.x); Ks[o + 1] = f2tf(kv.y);
            Ks[o + 2] = f2tf(kv.z); Ks[o + 3] = f2tf(kv.w);
        }
    }
    __syncthreads();

    float accS[8][4] = {};
    #pragma unroll
    for (int kk = 0; kk < 64; kk += 8) {
        int ar0 = (wm * 16 + g) * 68, ar1 = ar0 + 8 * 68;
        unsigned ah0 = Qh[ar0 + kk + t4],     ah1 = Qh[ar1 + kk + t4];
        unsigned ah2 = Qh[ar0 + kk + t4 + 4], ah3 = Qh[ar1 + kk + t4 + 4];
        #pragma unroll
        for (int nf = 0; nf < 8; nf++) {
            int nb = (wn * 64 + nf * 8 + g) * 68;
            mma8(accS[nf], ah0, ah1, ah2, ah3, Ks[nb + kk + t4], Ks[nb + kk + t4 + 4]);
        }
    }
    __syncthreads();

    {
        int row0 = wm * 16 + g, row1 = row0 + 8;
        #pragma unroll
        for (int nf = 0; nf < 8; nf++) {
            int col = wn * 64 + nf * 8 + 2 * t4;
            Sf[row0 * 260 + col] = accS[nf][0]; Sf[row0 * 260 + col + 1] = accS[nf][1];
            Sf[row1 * 260 + col] = accS[nf][2]; Sf[row1 * 260 + col + 1] = accS[nf][3];
        }
    }
    __syncthreads();

    float* hrow = hist + w * 520;
    for (int r = 0; r < 4; r++) {
        int row = w * 4 + r;
        int q = qt0 + row;
        int bq = (b << 8) | q;
        bool mq = g_mask[bq] != 0;
        long tmbase = (long)bq * 256;
        int qbase = (h * ROWS + bq) * TP;
        int t8[8]; float e[8];
        float inv = 1.f / 256.f;
        #pragma unroll
        for (int j = 0; j < 8; j++) t8[j] = tm[tmbase + lane + 32 * j];
        if (!mq) {
            float mx = -3.4e38f;
            #pragma unroll
            for (int j = 0; j < 8; j++) {
                int k = lane + 32 * j;
                float lg = (k <= q)
                    ? (Sf[row * 260 + k] + g_qtk[qbase + t8[j]]) * 0.125f : -1e30f;
                e[j] = lg; mx = fmaxf(mx, lg);
            }
            #pragma unroll
            for (int o = 16; o; o >>= 1) mx = fmaxf(mx, __shfl_xor_sync(~0u, mx, o));
            float sum = 0.f;
            #pragma unroll
            for (int j = 0; j < 8; j++) { e[j] = __expf(e[j] - mx); sum += e[j]; }
            #pragma unroll
            for (int o = 16; o; o >>= 1) sum += __shfl_xor_sync(~0u, sum, o);
            inv = 1.f / sum;
        }
        for (int t = lane; t < 520; t += 32) hrow[t] = 0.f;
        __syncwarp();
        #pragma unroll
        for (int j = 0; j < 8; j++) {
            int k = lane + 32 * j;
            float p = mq ? (1.f / 256.f) : e[j] * inv;
            Sf[row * 260 + k] = __uint_as_float(f2tf(p));
            atomicAdd(&hrow[t8[j]], p);
        }
        __syncwarp();
        for (int t = lane; t < TT; t += 32) g_w[qbase + t] = hrow[t];
    }
    __syncthreads();

    {
        int r = tid >> 1, cb = (tid & 1) * 32;
        const float* vp = g_V + (((b << 8) | r) << 8) + hd + cb;
        #pragma unroll
        for (int j = 0; j < 8; j++) {
            float4 vv = *(const float4*)(vp + 4 * j);
            Vs[(cb + 4 * j + 0) * 260 + r] = f2tf(vv.x);
            Vs[(cb + 4 * j + 1) * 260 + r] = f2tf(vv.y);
            Vs[(cb + 4 * j + 2) * 260 + r] = f2tf(vv.z);
            Vs[(cb + 4 * j + 3) * 260 + r] = f2tf(vv.w);
        }
    }
    __syncthreads();

    float accO[2][4] = {};
    const unsigned* Su = (const unsigned*)Sf;
    #pragma unroll 4
    for (int kk = 0; kk < 256; kk += 8) {
        int ar0 = (wm * 16 + g) * 260, ar1 = ar0 + 8 * 260;
        unsigned a0 = Su[ar0 + kk + t4],     a1 = Su[ar1 + kk + t4];
        unsigned a2 = Su[ar0 + kk + t4 + 4], a3 = Su[ar1 + kk + t4 + 4];
        #pragma unroll
        for (int nf = 0; nf < 2; nf++) {
            int nb = (wn * 16 + nf * 8 + g) * 260;
            mma8(accO[nf], a0, a1, a2, a3, Vs[nb + kk + t4], Vs[nb + kk + t4 + 4]);
        }
    }
    __syncthreads();

    unsigned* wS  = R1;                 // [64][68]
    unsigned* tVs = R2;                 // [64][68]
    for (int tt = 0; tt < TP; tt += 64) {
        int rr = tid >> 3, cg = (tid & 7) * 8;
        {
            const float* wp = g_w + ((h * ROWS + ((b << 8) | (qt0 + rr))) * TP) + tt + cg;
            float4 a0 = *(const float4*)wp, a1 = *(const float4*)(wp + 4);
            float bw[8] = {a0.x, a0.y, a0.z, a0.w, a1.x, a1.y, a1.z, a1.w};
            #pragma unroll
            for (int j = 0; j < 8; j++) wS[rr * 68 + cg + j] = f2tf(bw[j]);
            int trow = tt + rr;
            float4 v0 = make_float4(0.f, 0.f, 0.f, 0.f), v1 = v0;
            if (trow < TT) {
                const float* vp = tV + trow * H_ + hd + cg;
                v0 = *(const float4*)vp; v1 = *(const float4*)(vp + 4);
            }
            float bv[8] = {v0.x, v0.y, v0.z, v0.w, v1.x, v1.y, v1.z, v1.w};
            #pragma unroll
            for (int j = 0; j < 8; j++) tVs[(cg + j) * 68 + rr] = f2tf(bv[j]);
        }
        __syncthreads();
        #pragma unroll
        for (int kk = 0; kk < 64; kk += 8) {
            int ar0 = (wm * 16 + g) * 68, ar1 = ar0 + 8 * 68;
            unsigned a0 = wS[ar0 + kk + t4],     a1 = wS[ar1 + kk + t4];
            unsigned a2 = wS[ar0 + kk + t4 + 4], a3 = wS[ar1 + kk + t4 + 4];
            #pragma unroll
            for (int nf = 0; nf < 2; nf++) {
                int nb = (wn * 16 + nf * 8 + g) * 68;
                mma8(accO[nf], a0, a1, a2, a3, tVs[nb + kk + t4], tVs[nb + kk + t4 + 4]);
            }
        }
        __syncthreads();
    }

    {
        int q0g = qt0 + wm * 16 + g;
        #pragma unroll
        for (int nf = 0; nf < 2; nf++) {
            int col = hd + wn * 16 + nf * 8 + 2 * t4;
            *(float2*)(g_att + (((b << 8) | q0g) << 8) + col) =
                make_float2(accO[nf][0], accO[nf][1]);
            *(float2*)(g_att + (((b << 8) | (q0g + 8)) << 8) + col) =
                make_float2(accO[nf][2], accO[nf][3]);
        }
    }
}

extern "C" void kernel_launch(void* const* d_in, const int* in_sizes, int n_in,
                              void* d_out, int out_size) {
    const void*  mraw = d_in[0];
    const float* seq  = (const float*)d_in[1];
    const int*   tm   = (const int*)d_in[3];
    int base = (n_in >= 25 && in_sizes[4] == 1) ? 5 : 4;
    const float* Wq   = (const float*)d_in[base + 0];  const float* bq  = (const float*)d_in[base + 1];
    const float* Wk   = (const float*)d_in[base + 2];  const float* bk  = (const float*)d_in[base + 3];
    const float* Wv   = (const float*)d_in[base + 4];  const float* bv  = (const float*)d_in[base + 5];
    const float* ln1g = (const float*)d_in[base + 6];  const float* ln1b = (const float*)d_in[base + 7];
    const float* ln2g = (const float*)d_in[base + 8];  const float* ln2b = (const float*)d_in[base + 9];
    const float* W1   = (const float*)d_in[base + 10]; const float* b1  = (const float*)d_in[base + 11];
    const float* W2   = (const float*)d_in[base + 12]; const float* b2  = (const float*)d_in[base + 13];
    const float* posK = (const float*)d_in[base + 14]; const float* posV = (const float*)d_in[base + 15];
    const float* tK   = (const float*)d_in[base + 16]; const float* tV  = (const float*)d_in[base + 17];
    const float* lnfg = (const float*)d_in[base + 18]; const float* lnfb = (const float*)d_in[base + 19];
    float* out = (float*)d_out;

    float *px, *pq, *pQ, *pK, *pV, *patt, *pxa, *ph;
    cudaGetSymbolAddress((void**)&px,  g_x);
    cudaGetSymbolAddress((void**)&pq,  g_q);
    cudaGetSymbolAddress((void**)&pQ,  g_Q);
    cudaGetSymbolAddress((void**)&pK,  g_K);
    cudaGetSymbolAddress((void**)&pV,  g_V);
    cudaGetSymbolAddress((void**)&patt, g_att);
    cudaGetSymbolAddress((void**)&pxa, g_xa);
    cudaGetSymbolAddress((void**)&ph,  g_h);

    cudaFuncSetAttribute(k_attn2, cudaFuncAttributeMaxDynamicSharedMemorySize, SMEM_ATTN2);

    k_mask_convert<<<1, 256>>>(mraw);
    k_maskmul<<<PLANE / 256, 256>>>(seq);
    for (int i = 0; i < NBLK; i++) {
        const float* wq = Wq + (long)i * H_ * H_;
        const float* wk = Wk + (long)i * H_ * H_;
        const float* wv = Wv + (long)i * H_ * H_;
        const float* w1 = W1 + (long)i * H_ * H_;
        const float* w2 = W2 + (long)i * H_ * H_;

        // QKV: job0 = LN1(x) @ Wq (fused LN, writes g_q); jobs 1,2 raw x.
        TJobs jq;
        jq.j[0] = {px, nullptr, ln1g + i * H_, ln1b + i * H_, pq, 1,
                   wq, bq + i * H_, nullptr, pQ, 0};
        jq.j[1] = {px, nullptr, nullptr, nullptr, nullptr, 0,
                   wk, bk + i * H_, posK, pK, 1};
        jq.j[2] = {px, nullptr, nullptr, nullptr, nullptr, 0,
                   wv, bv + i * H_, posV, pV, 2};
        k_gemm_tc<<<dim3(4, 64, 3), 128>>>(jq);

        k_qtk<<<dim3(TP / 64, ROWS / 64, NH), 256>>>(tK);
        k_attn2<<<dim3(4, B_, NH), 512, SMEM_ATTN2>>>(tm, tV);

        // FFN1: LN2(q + att) @ W1 with relu (fused LN, writes g_xa).
        TJobs j1;
        j1.j[0] = {pq, patt, ln2g + i * H_, ln2b + i * H_, pxa, 1,
                   w1, b1 + i * H_, nullptr, ph, 3};
        j1.j[1] = j1.j[0]; j1.j[2] = j1.j[0];
        k_gemm_tc<<<dim3(4, 64, 1), 128>>>(j1);

        // FFN2: h @ W2 + b2 + xa, * keep.
        TJobs j2;
        j2.j[0] = {ph, nullptr, nullptr, nullptr, nullptr, 0,
                   w2, b2 + i * H_, pxa, px, 4};
        j2.j[1] = j2.j[0]; j2.j[2] = j2.j[0];
        k_gemm_tc<<<dim3(4, 64, 1), 128>>>(j2);
    }
    k_ln<<<ROWS / 8, 256>>>(px, nullptr, lnfg, lnfb, out);
}

// round 17
// speedup vs baseline: 1.5890x; 1.5890x over previous
#include <cuda_runtime.h>
#include <math.h>

namespace {
constexpr int B_ = 8, L_ = 256, H_ = 256, NH = 4, D_ = 64, NBLK = 2;
constexpr int ROWS = B_ * L_;          // 2048
constexpr int PLANE = ROWS * H_;       // 524288
constexpr int TT = 513;                // TSPAN+1 time rows
constexpr int TP = 576;                // padded
}

// ---- scratch ----
__device__ float g_x[PLANE];
__device__ float g_q[PLANE];
__device__ float g_Q[PLANE];
__device__ float g_K[PLANE];
__device__ float g_V[PLANE];
__device__ float g_att[PLANE];
__device__ float g_xa[PLANE];
__device__ float g_h[PLANE];
__device__ float g_qtk[NH * ROWS * TP];      // QtK table [h][bq][t]
__device__ float g_w[NH * ROWS * TP];        // histogram weights (.bss zero; pad never written)
__device__ unsigned char g_mask[ROWS];

struct TJob { const float* A; const float* W; const float* bias;
              const float* aux; float* C; int mode; };
struct TJobs { TJob j[3]; };

// ---- mask dtype sniffer + converter ----
__global__ void k_mask_convert(const void* __restrict__ mraw) {
    __shared__ int s_f32, s_u8;
    const unsigned int* w = (const unsigned int*)mraw;
    int t = threadIdx.x;
    if (t == 0) { s_f32 = 0; s_u8 = 0; }
    __syncthreads();
    for (int i = t; i < 512; i += 256) {
        unsigned int v = w[i];
        if (v == 0x3F800000u) atomicOr(&s_f32, 1);
        if (v & 0xFFFFFF00u)  atomicOr(&s_u8, 1);
    }
    __syncthreads();
    int mode = s_f32 ? 2 : (s_u8 ? 0 : 1);
    const unsigned char* u8 = (const unsigned char*)mraw;
    const int* i32 = (const int*)mraw;
    const float* f32 = (const float*)mraw;
    for (int i = t; i < ROWS; i += 256) {
        unsigned char m;
        if (mode == 0)      m = u8[i] ? 1 : 0;
        else if (mode == 1) m = i32[i] ? 1 : 0;
        else                m = (f32[i] != 0.f) ? 1 : 0;
        g_mask[i] = m;
    }
}

__global__ void k_maskmul(const float* __restrict__ e) {
    int i = blockIdx.x * blockDim.x + threadIdx.x;
    g_x[i] = g_mask[i >> 8] ? 0.f : e[i];
}

// out = LN(in1 (+ in2)) * g + b  — warp per row, shfl-only reductions.
__global__ __launch_bounds__(256) void k_ln(const float* __restrict__ in1,
                                            const float* __restrict__ in2,
                                            const float* __restrict__ gg,
                                            const float* __restrict__ bb,
                                            float* __restrict__ out) {
    int row = blockIdx.x * 8 + (threadIdx.x >> 5);
    int lane = threadIdx.x & 31;
    const float* p1 = in1 + row * H_;
    float v[8];
    float s = 0.f;
    #pragma unroll
    for (int j = 0; j < 8; j++) {
        v[j] = p1[lane + 32 * j];
        if (in2) v[j] += in2[row * H_ + lane + 32 * j];
        s += v[j];
    }
    #pragma unroll
    for (int o = 16; o; o >>= 1) s += __shfl_xor_sync(~0u, s, o);
    float m = s * (1.f / H_);
    float sq = 0.f;
    #pragma unroll
    for (int j = 0; j < 8; j++) { float d = v[j] - m; sq += d * d; }
    #pragma unroll
    for (int o = 16; o; o >>= 1) sq += __shfl_xor_sync(~0u, sq, o);
    float inv = rsqrtf(sq * (1.f / H_) + 1e-8f);
    #pragma unroll
    for (int j = 0; j < 8; j++) {
        int c = lane + 32 * j;
        out[row * H_ + c] = (v[j] - m) * inv * gg[c] + bb[c];
    }
}

// ---- tf32 mma helpers ----
__device__ __forceinline__ unsigned f2tf(float f) {
    unsigned u;
    asm("cvt.rna.tf32.f32 %0, %1;" : "=r"(u) : "f"(f));
    return u;
}
__device__ __forceinline__ void mma8(float* d, unsigned a0, unsigned a1,
                                     unsigned a2, unsigned a3,
                                     unsigned b0, unsigned b1) {
    asm volatile(
        "mma.sync.aligned.m16n8k8.row.col.f32.tf32.tf32.f32 "
        "{%0,%1,%2,%3}, {%4,%5,%6,%7}, {%8,%9}, {%0,%1,%2,%3};"
        : "+f"(d[0]), "+f"(d[1]), "+f"(d[2]), "+f"(d[3])
        : "r"(a0), "r"(a1), "r"(a2), "r"(a3), "r"(b0), "r"(b1));
}

// ---- shared epilogue ----
__device__ __forceinline__ void gemm_epilogue(
        const TJob& J, int row0, int row1, int col, const float* a4) {
    float b0 = J.bias[col], b1 = J.bias[col + 1];
    float v00 = a4[0] + b0, v01 = a4[1] + b1;
    float v10 = a4[2] + b0, v11 = a4[3] + b1;
    int mode = J.mode;
    if (mode == 1 || mode == 2) {
        const float* pos = J.aux;
        v00 += pos[((row0 & 255) << 8) | col];
        v01 += pos[((row0 & 255) << 8) | (col + 1)];
        v10 += pos[((row1 & 255) << 8) | col];
        v11 += pos[((row1 & 255) << 8) | (col + 1)];
    } else if (mode == 3) {
        v00 = fmaxf(v00, 0.f); v01 = fmaxf(v01, 0.f);
        v10 = fmaxf(v10, 0.f); v11 = fmaxf(v11, 0.f);
    } else if (mode == 4) {
        v00 += J.aux[row0 * H_ + col]; v01 += J.aux[row0 * H_ + col + 1];
        v10 += J.aux[row1 * H_ + col]; v11 += J.aux[row1 * H_ + col + 1];
        if (g_mask[row0]) { v00 = 0.f; v01 = 0.f; }
        if (g_mask[row1]) { v10 = 0.f; v11 = 0.f; }
    }
    *(float2*)(J.C + row0 * H_ + col) = make_float2(v00, v01);
    *(float2*)(J.C + row1 * H_ + col) = make_float2(v10, v11);
}

// PLAIN tf32 GEMM, 64x64 tile, warp=32x32 (R14-proven; best for QKV, 384 blocks).
__global__ __launch_bounds__(128) void k_gemm64(TJobs jobs) {
    const TJob J = jobs.j[blockIdx.z];
    __shared__ unsigned As[64][36], Ws[64][36];
    int tid = threadIdx.x;
    int w = tid >> 5, lane = tid & 31;
    int wm = w & 1, wn = w >> 1;
    int o0 = blockIdx.x * 64, i0 = blockIdx.y * 64;
    int g = lane >> 2, t4 = lane & 3;
    int sr = tid >> 1, sc = (tid & 1) * 16;
    const float* Ap = J.A + (i0 + sr) * H_ + sc;
    const float* Wp = J.W + (o0 + sr) * H_ + sc;
    float acc[2][4][4] = {};
    float4 av[4], wv4[4];
    #pragma unroll
    for (int j = 0; j < 4; j++) {
        av[j]  = *(const float4*)(Ap + 4 * j);
        wv4[j] = *(const float4*)(Wp + 4 * j);
    }
    #pragma unroll
    for (int tile = 0; tile < 8; tile++) {
        #pragma unroll
        for (int j = 0; j < 4; j++) {
            int c = sc + 4 * j;
            As[sr][c + 0] = f2tf(av[j].x); As[sr][c + 1] = f2tf(av[j].y);
            As[sr][c + 2] = f2tf(av[j].z); As[sr][c + 3] = f2tf(av[j].w);
            Ws[sr][c + 0] = f2tf(wv4[j].x); Ws[sr][c + 1] = f2tf(wv4[j].y);
            Ws[sr][c + 2] = f2tf(wv4[j].z); Ws[sr][c + 3] = f2tf(wv4[j].w);
        }
        __syncthreads();
        if (tile < 7) {
            #pragma unroll
            for (int j = 0; j < 4; j++) {
                av[j]  = *(const float4*)(Ap + (tile + 1) * 32 + 4 * j);
                wv4[j] = *(const float4*)(Wp + (tile + 1) * 32 + 4 * j);
            }
        }
        #pragma unroll
        for (int kk = 0; kk < 32; kk += 8) {
            unsigned ah[2][4];
            #pragma unroll
            for (int mf = 0; mf < 2; mf++) {
                int ar0 = wm * 32 + mf * 16 + g, ar1 = ar0 + 8;
                ah[mf][0] = As[ar0][kk + t4];     ah[mf][1] = As[ar1][kk + t4];
                ah[mf][2] = As[ar0][kk + t4 + 4]; ah[mf][3] = As[ar1][kk + t4 + 4];
            }
            #pragma unroll
            for (int nf = 0; nf < 4; nf++) {
                int nb = wn * 32 + nf * 8 + g;
                unsigned b0 = Ws[nb][kk + t4], b1 = Ws[nb][kk + t4 + 4];
                #pragma unroll
                for (int mf = 0; mf < 2; mf++)
                    mma8(acc[mf][nf], ah[mf][0], ah[mf][1], ah[mf][2], ah[mf][3], b0, b1);
            }
        }
        __syncthreads();
    }
    #pragma unroll
    for (int mf = 0; mf < 2; mf++) {
        int row0 = i0 + wm * 32 + mf * 16 + g, row1 = row0 + 8;
        #pragma unroll
        for (int nf = 0; nf < 4; nf++)
            gemm_epilogue(J, row0, row1, o0 + wn * 32 + nf * 8 + 2 * t4, acc[mf][nf]);
    }
}

// PLAIN tf32 GEMM, 32x64 tile, warp=16x32 (R15-proven; best for FFN, 256 blocks).
__global__ __launch_bounds__(128) void k_gemm32(TJobs jobs) {
    const TJob J = jobs.j[blockIdx.z];
    __shared__ unsigned As[32][36], Ws[64][36];
    int tid = threadIdx.x;
    int w = tid >> 5, lane = tid & 31;
    int wm = w & 1, wn = w >> 1;
    int o0 = blockIdx.x * 64, i0 = blockIdx.y * 32;
    int g = lane >> 2, t4 = lane & 3;
    int asr = tid >> 2, asc = (tid & 3) * 8;
    int wsr = tid >> 1, wsc = (tid & 1) * 16;
    const float* Ap = J.A + (i0 + asr) * H_ + asc;
    const float* Wp = J.W + (o0 + wsr) * H_ + wsc;
    float acc[4][4] = {};
    float4 av0 = *(const float4*)Ap, av1 = *(const float4*)(Ap + 4);
    float4 wv[4];
    #pragma unroll
    for (int j = 0; j < 4; j++) wv[j] = *(const float4*)(Wp + 4 * j);
    #pragma unroll
    for (int tile = 0; tile < 8; tile++) {
        As[asr][asc + 0] = f2tf(av0.x); As[asr][asc + 1] = f2tf(av0.y);
        As[asr][asc + 2] = f2tf(av0.z); As[asr][asc + 3] = f2tf(av0.w);
        As[asr][asc + 4] = f2tf(av1.x); As[asr][asc + 5] = f2tf(av1.y);
        As[asr][asc + 6] = f2tf(av1.z); As[asr][asc + 7] = f2tf(av1.w);
        #pragma unroll
        for (int j = 0; j < 4; j++) {
            int c = wsc + 4 * j;
            Ws[wsr][c + 0] = f2tf(wv[j].x); Ws[wsr][c + 1] = f2tf(wv[j].y);
            Ws[wsr][c + 2] = f2tf(wv[j].z); Ws[wsr][c + 3] = f2tf(wv[j].w);
        }
        __syncthreads();
        if (tile < 7) {
            av0 = *(const float4*)(Ap + (tile + 1) * 32);
            av1 = *(const float4*)(Ap + (tile + 1) * 32 + 4);
            #pragma unroll
            for (int j = 0; j < 4; j++)
                wv[j] = *(const float4*)(Wp + (tile + 1) * 32 + 4 * j);
        }
        #pragma unroll
        for (int kk = 0; kk < 32; kk += 8) {
            int ar0 = wm * 16 + g, ar1 = ar0 + 8;
            unsigned a0 = As[ar0][kk + t4],     a1 = As[ar1][kk + t4];
            unsigned a2 = As[ar0][kk + t4 + 4], a3 = As[ar1][kk + t4 + 4];
            #pragma unroll
            for (int nf = 0; nf < 4; nf++) {
                int nb = wn * 32 + nf * 8 + g;
                mma8(acc[nf], a0, a1, a2, a3, Ws[nb][kk + t4], Ws[nb][kk + t4 + 4]);
            }
        }
        __syncthreads();
    }
    int row0 = i0 + wm * 16 + g, row1 = row0 + 8;
    #pragma unroll
    for (int nf = 0; nf < 4; nf++)
        gemm_epilogue(J, row0, row1, o0 + wn * 32 + nf * 8 + 2 * t4, acc[nf]);
}

// QtK table, PLAIN tf32, SINGLE staging round (K=64 staged at once).
__global__ __launch_bounds__(256) void k_qtk(const float* __restrict__ tK) {
    __shared__ unsigned As[64][68], Ws[64][68];
    int h = blockIdx.z, hd = h << 6;
    int t0 = blockIdx.x * 64, i0 = blockIdx.y * 64;
    int tid = threadIdx.x;
    int w = tid >> 5, lane = tid & 31;
    int wm = w & 3, wn = w >> 2;
    int g = lane >> 2, t4 = lane & 3;
    int sr = tid >> 2, sc = (tid & 3) * 16;
    {
        const float* ap = g_Q + (i0 + sr) * H_ + hd + sc;
        #pragma unroll
        for (int j = 0; j < 4; j++) {
            float4 v = *(const float4*)(ap + 4 * j);
            int c = sc + 4 * j;
            As[sr][c + 0] = f2tf(v.x); As[sr][c + 1] = f2tf(v.y);
            As[sr][c + 2] = f2tf(v.z); As[sr][c + 3] = f2tf(v.w);
        }
        int trow = t0 + sr;
        #pragma unroll
        for (int j = 0; j < 4; j++) {
            float4 v = make_float4(0.f, 0.f, 0.f, 0.f);
            if (trow < TT) v = *(const float4*)(tK + trow * H_ + hd + sc + 4 * j);
            int c = sc + 4 * j;
            Ws[sr][c + 0] = f2tf(v.x); Ws[sr][c + 1] = f2tf(v.y);
            Ws[sr][c + 2] = f2tf(v.z); Ws[sr][c + 3] = f2tf(v.w);
        }
    }
    __syncthreads();
    float acc[4][4] = {};
    #pragma unroll
    for (int kk = 0; kk < 64; kk += 8) {
        int ar0 = wm * 16 + g, ar1 = ar0 + 8;
        unsigned a0 = As[ar0][kk + t4],     a1 = As[ar1][kk + t4];
        unsigned a2 = As[ar0][kk + t4 + 4], a3 = As[ar1][kk + t4 + 4];
        #pragma unroll
        for (int nf = 0; nf < 4; nf++) {
            int nb = wn * 32 + nf * 8 + g;
            mma8(acc[nf], a0, a1, a2, a3, Ws[nb][kk + t4], Ws[nb][kk + t4 + 4]);
        }
    }
    int row0 = i0 + wm * 16 + g, row1 = row0 + 8;
    #pragma unroll
    for (int nf = 0; nf < 4; nf++) {
        int col = t0 + wn * 32 + nf * 8 + 2 * t4;
        int ia = (h * ROWS + row0) * TP + col;
        int ib = (h * ROWS + row1) * TP + col;
        *(float2*)(g_qtk + ia) = make_float2(acc[nf][0], acc[nf][1]);
        *(float2*)(g_qtk + ib) = make_float2(acc[nf][2], acc[nf][3]);
    }
}

// ===== Fused attention core (R15-proven): S=QK^T -> softmax(+qtk) ->
//       histogram -> out = P@V + w@tV. Block per (64q-tile, b, h). =====
constexpr int SMEM_ATTN2 = (256 * 68 + 64 * 260) * 4;
__global__ __launch_bounds__(512) void k_attn2(const int* __restrict__ tm,
                                               const float* __restrict__ tV) {
    extern __shared__ unsigned sm2[];
    unsigned* R1 = sm2;
    unsigned* R2 = sm2 + 256 * 68;
    float*    Sf = (float*)R1;
    unsigned* Ks = R1;
    unsigned* Qh = R2;
    float*  hist = (float*)R2;
    unsigned* Vs = R2;

    int qt0 = blockIdx.x * 64;
    int b = blockIdx.y, h = blockIdx.z, hd = h << 6;
    int tid = threadIdx.x, w = tid >> 5, lane = tid & 31;
    int g = lane >> 2, t4 = lane & 3;
    int wm = w & 3, wn = w >> 2;

    {
        int sr = tid >> 3, sc = (tid & 7) * 8;
        const float* qp = g_Q + (((b << 8) | (qt0 + sr)) << 8) + hd + sc;
        float4 v0 = *(const float4*)qp, v1 = *(const float4*)(qp + 4);
        float buf[8] = {v0.x, v0.y, v0.z, v0.w, v1.x, v1.y, v1.z, v1.w};
        #pragma unroll
        for (int j = 0; j < 8; j++)
            Qh[sr * 68 + sc + j] = f2tf(buf[j]);
    }
    {
        int r = tid >> 1, cb = (tid & 1) * 32;
        const float* kp = g_K + (((b << 8) | r) << 8) + hd + cb;
        #pragma unroll
        for (int j = 0; j < 8; j++) {
            float4 kv = *(const float4*)(kp + 4 * j);
            int o = r * 68 + cb + 4 * j;
            Ks[o + 0] = f2tf(kv.x); Ks[o + 1] = f2tf(kv.y);
            Ks[o + 2] = f2tf(kv.z); Ks[o + 3] = f2tf(kv.w);
        }
    }
    __syncthreads();

    float accS[8][4] = {};
    #pragma unroll
    for (int kk = 0; kk < 64; kk += 8) {
        int ar0 = (wm * 16 + g) * 68, ar1 = ar0 + 8 * 68;
        unsigned ah0 = Qh[ar0 + kk + t4],     ah1 = Qh[ar1 + kk + t4];
        unsigned ah2 = Qh[ar0 + kk + t4 + 4], ah3 = Qh[ar1 + kk + t4 + 4];
        #pragma unroll
        for (int nf = 0; nf < 8; nf++) {
            int nb = (wn * 64 + nf * 8 + g) * 68;
            mma8(accS[nf], ah0, ah1, ah2, ah3, Ks[nb + kk + t4], Ks[nb + kk + t4 + 4]);
        }
    }
    __syncthreads();

    {
        int row0 = wm * 16 + g, row1 = row0 + 8;
        #pragma unroll
        for (int nf = 0; nf < 8; nf++) {
            int col = wn * 64 + nf * 8 + 2 * t4;
            Sf[row0 * 260 + col] = accS[nf][0]; Sf[row0 * 260 + col + 1] = accS[nf][1];
            Sf[row1 * 260 + col] = accS[nf][2]; Sf[row1 * 260 + col + 1] = accS[nf][3];
        }
    }
    __syncthreads();

    float* hrow = hist + w * 520;
    for (int r = 0; r < 4; r++) {
        int row = w * 4 + r;
        int q = qt0 + row;
        int bq = (b << 8) | q;
        bool mq = g_mask[bq] != 0;
        long tmbase = (long)bq * 256;
        int qbase = (h * ROWS + bq) * TP;
        int t8[8]; float e[8];
        float inv = 1.f / 256.f;
        #pragma unroll
        for (int j = 0; j < 8; j++) t8[j] = tm[tmbase + lane + 32 * j];
        if (!mq) {
            float mx = -3.4e38f;
            #pragma unroll
            for (int j = 0; j < 8; j++) {
                int k = lane + 32 * j;
                float lg = (k <= q)
                    ? (Sf[row * 260 + k] + g_qtk[qbase + t8[j]]) * 0.125f : -1e30f;
                e[j] = lg; mx = fmaxf(mx, lg);
            }
            #pragma unroll
            for (int o = 16; o; o >>= 1) mx = fmaxf(mx, __shfl_xor_sync(~0u, mx, o));
            float sum = 0.f;
            #pragma unroll
            for (int j = 0; j < 8; j++) { e[j] = __expf(e[j] - mx); sum += e[j]; }
            #pragma unroll
            for (int o = 16; o; o >>= 1) sum += __shfl_xor_sync(~0u, sum, o);
            inv = 1.f / sum;
        }
        for (int t = lane; t < 520; t += 32) hrow[t] = 0.f;
        __syncwarp();
        #pragma unroll
        for (int j = 0; j < 8; j++) {
            int k = lane + 32 * j;
            float p = mq ? (1.f / 256.f) : e[j] * inv;
            Sf[row * 260 + k] = __uint_as_float(f2tf(p));
            atomicAdd(&hrow[t8[j]], p);
        }
        __syncwarp();
        for (int t = lane; t < TT; t += 32) g_w[qbase + t] = hrow[t];
    }
    __syncthreads();

    {
        int r = tid >> 1, cb = (tid & 1) * 32;
        const float* vp = g_V + (((b << 8) | r) << 8) + hd + cb;
        #pragma unroll
        for (int j = 0; j < 8; j++) {
            float4 vv = *(const float4*)(vp + 4 * j);
            Vs[(cb + 4 * j + 0) * 260 + r] = f2tf(vv.x);
            Vs[(cb + 4 * j + 1) * 260 + r] = f2tf(vv.y);
            Vs[(cb + 4 * j + 2) * 260 + r] = f2tf(vv.z);
            Vs[(cb + 4 * j + 3) * 260 + r] = f2tf(vv.w);
        }
    }
    __syncthreads();

    float accO[2][4] = {};
    const unsigned* Su = (const unsigned*)Sf;
    #pragma unroll 4
    for (int kk = 0; kk < 256; kk += 8) {
        int ar0 = (wm * 16 + g) * 260, ar1 = ar0 + 8 * 260;
        unsigned a0 = Su[ar0 + kk + t4],     a1 = Su[ar1 + kk + t4];
        unsigned a2 = Su[ar0 + kk + t4 + 4], a3 = Su[ar1 + kk + t4 + 4];
        #pragma unroll
        for (int nf = 0; nf < 2; nf++) {
            int nb = (wn * 16 + nf * 8 + g) * 260;
            mma8(accO[nf], a0, a1, a2, a3, Vs[nb + kk + t4], Vs[nb + kk + t4 + 4]);
        }
    }
    __syncthreads();

    unsigned* wS  = R1;
    unsigned* tVs = R2;
    for (int tt = 0; tt < TP; tt += 64) {
        int rr = tid >> 3, cg = (tid & 7) * 8;
        {
            const float* wp = g_w + ((h * ROWS + ((b << 8) | (qt0 + rr))) * TP) + tt + cg;
            float4 a0 = *(const float4*)wp, a1 = *(const float4*)(wp + 4);
            float bw[8] = {a0.x, a0.y, a0.z, a0.w, a1.x, a1.y, a1.z, a1.w};
            #pragma unroll
            for (int j = 0; j < 8; j++) wS[rr * 68 + cg + j] = f2tf(bw[j]);
            int trow = tt + rr;
            float4 v0 = make_float4(0.f, 0.f, 0.f, 0.f), v1 = v0;
            if (trow < TT) {
                const float* vp = tV + trow * H_ + hd + cg;
                v0 = *(const float4*)vp; v1 = *(const float4*)(vp + 4);
            }
            float bv[8] = {v0.x, v0.y, v0.z, v0.w, v1.x, v1.y, v1.z, v1.w};
            #pragma unroll
            for (int j = 0; j < 8; j++) tVs[(cg + j) * 68 + rr] = f2tf(bv[j]);
        }
        __syncthreads();
        #pragma unroll
        for (int kk = 0; kk < 64; kk += 8) {
            int ar0 = (wm * 16 + g) * 68, ar1 = ar0 + 8 * 68;
            unsigned a0 = wS[ar0 + kk + t4],     a1 = wS[ar1 + kk + t4];
            unsigned a2 = wS[ar0 + kk + t4 + 4], a3 = wS[ar1 + kk + t4 + 4];
            #pragma unroll
            for (int nf = 0; nf < 2; nf++) {
                int nb = (wn * 16 + nf * 8 + g) * 68;
                mma8(accO[nf], a0, a1, a2, a3, tVs[nb + kk + t4], tVs[nb + kk + t4 + 4]);
            }
        }
        __syncthreads();
    }

    {
        int q0g = qt0 + wm * 16 + g;
        #pragma unroll
        for (int nf = 0; nf < 2; nf++) {
            int col = hd + wn * 16 + nf * 8 + 2 * t4;
            *(float2*)(g_att + (((b << 8) | q0g) << 8) + col) =
                make_float2(accO[nf][0], accO[nf][1]);
            *(float2*)(g_att + (((b << 8) | (q0g + 8)) << 8) + col) =
                make_float2(accO[nf][2], accO[nf][3]);
        }
    }
}

extern "C" void kernel_launch(void* const* d_in, const int* in_sizes, int n_in,
                              void* d_out, int out_size) {
    const void*  mraw = d_in[0];
    const float* seq  = (const float*)d_in[1];
    const int*   tm   = (const int*)d_in[3];
    int base = (n_in >= 25 && in_sizes[4] == 1) ? 5 : 4;
    const float* Wq   = (const float*)d_in[base + 0];  const float* bq  = (const float*)d_in[base + 1];
    const float* Wk   = (const float*)d_in[base + 2];  const float* bk  = (const float*)d_in[base + 3];
    const float* Wv   = (const float*)d_in[base + 4];  const float* bv  = (const float*)d_in[base + 5];
    const float* ln1g = (const float*)d_in[base + 6];  const float* ln1b = (const float*)d_in[base + 7];
    const float* ln2g = (const float*)d_in[base + 8];  const float* ln2b = (const float*)d_in[base + 9];
    const float* W1   = (const float*)d_in[base + 10]; const float* b1  = (const float*)d_in[base + 11];
    const float* W2   = (const float*)d_in[base + 12]; const float* b2  = (const float*)d_in[base + 13];
    const float* posK = (const float*)d_in[base + 14]; const float* posV = (const float*)d_in[base + 15];
    const float* tK   = (const float*)d_in[base + 16]; const float* tV  = (const float*)d_in[base + 17];
    const float* lnfg = (const float*)d_in[base + 18]; const float* lnfb = (const float*)d_in[base + 19];
    float* out = (float*)d_out;

    float *px, *pq, *pQ, *pK, *pV, *patt, *pxa, *ph;
    cudaGetSymbolAddress((void**)&px,  g_x);
    cudaGetSymbolAddress((void**)&pq,  g_q);
    cudaGetSymbolAddress((void**)&pQ,  g_Q);
    cudaGetSymbolAddress((void**)&pK,  g_K);
    cudaGetSymbolAddress((void**)&pV,  g_V);
    cudaGetSymbolAddress((void**)&patt, g_att);
    cudaGetSymbolAddress((void**)&pxa, g_xa);
    cudaGetSymbolAddress((void**)&ph,  g_h);

    cudaFuncSetAttribute(k_attn2, cudaFuncAttributeMaxDynamicSharedMemorySize, SMEM_ATTN2);

    k_mask_convert<<<1, 256>>>(mraw);
    k_maskmul<<<PLANE / 256, 256>>>(seq);
    for (int i = 0; i < NBLK; i++) {
        const float* wq = Wq + (long)i * H_ * H_;
        const float* wk = Wk + (long)i * H_ * H_;
        const float* wv = Wv + (long)i * H_ * H_;
        const float* w1 = W1 + (long)i * H_ * H_;
        const float* w2 = W2 + (long)i * H_ * H_;

        k_ln<<<ROWS / 8, 256>>>(px, nullptr, ln1g + i * H_, ln1b + i * H_, pq);

        TJobs jq;
        jq.j[0] = {pq, wq, bq + i * H_, nullptr, pQ, 0};
        jq.j[1] = {px, wk, bk + i * H_, posK,    pK, 1};
        jq.j[2] = {px, wv, bv + i * H_, posV,    pV, 2};
        k_gemm64<<<dim3(4, 32, 3), 128>>>(jq);

        k_qtk<<<dim3(TP / 64, ROWS / 64, NH), 256>>>(tK);
        k_attn2<<<dim3(4, B_, NH), 512, SMEM_ATTN2>>>(tm, tV);

        k_ln<<<ROWS / 8, 256>>>(pq, patt, ln2g + i * H_, ln2b + i * H_, pxa);

        TJobs j1;
        j1.j[0] = {pxa, w1, b1 + i * H_, nullptr, ph, 3};
        j1.j[1] = j1.j[0]; j1.j[2] = j1.j[0];
        k_gemm32<<<dim3(4, 64, 1), 128>>>(j1);

        TJobs j2;
        j2.j[0] = {ph, w2, b2 + i * H_, pxa, px, 4};
        j2.j[1] = j2.j[0]; j2.j[2] = j2.j[0];
        k_gemm32<<<dim3(4, 64, 1), 128>>>(j2);
    }
    k_ln<<<ROWS / 8, 256>>>(px, nullptr, lnfg, lnfb, out);
}